// round 1
// baseline (speedup 1.0000x reference)
#include <cuda_runtime.h>
#include <cstdint>
#include <cstddef>

#define NTIME 20
#define V     128
#define F     128
#define LRELU_ALPHA 0.2f

// out tuple layout: elu(h_prime) [20*128*128] then attention_raw [20*128*128*128]
#define OUT_HP_ELEMS   (NTIME * V * F)
#define ATT_OFF        OUT_HP_ELEMS

// Scratch (device globals: no allocation allowed in kernel_launch)
__device__ float g_Wh[NTIME * V * F];
__device__ float g_e1[NTIME * V * F];
__device__ float g_e2[NTIME * V * F];

// ----------------------------------------------------------------------------
// Kernel 1: fused  Wh = h @ W ;  e1 = Wh @ a[:128] ;  e2 = Wh @ a[128:]
// One block computes MT=16 rows. 256 threads: f = tid&127, half = tid>>7,
// each thread accumulates 8 rows for its column f.
// ----------------------------------------------------------------------------
#define MT 16

__global__ void __launch_bounds__(256) gemm_fused(
    const float* __restrict__ h,
    const float* __restrict__ W,
    const float* __restrict__ a)
{
    __shared__ float hs[MT * F];   // hs[row*F + k]
    __shared__ float whs[MT * F];  // whs[row*F + k]

    const int tid  = threadIdx.x;
    const int f    = tid & 127;
    const int half = tid >> 7;
    const int m0   = blockIdx.x * MT;

    // load h tile (2048 floats = 512 float4; 2 per thread)
    {
        const float4* h4  = (const float4*)(h + (size_t)m0 * F);
        float4*       hs4 = (float4*)hs;
        hs4[tid]       = h4[tid];
        hs4[tid + 256] = h4[tid + 256];
    }
    __syncthreads();

    float acc[8];
#pragma unroll
    for (int r = 0; r < 8; r++) acc[r] = 0.0f;

#pragma unroll 4
    for (int k = 0; k < F; k++) {
        const float wv = __ldg(W + k * F + f);
#pragma unroll
        for (int r = 0; r < 8; r++)
            acc[r] = fmaf(hs[(half * 8 + r) * F + k], wv, acc[r]);
    }

#pragma unroll
    for (int r = 0; r < 8; r++) {
        const int row = half * 8 + r;
        whs[row * F + f] = acc[r];
        g_Wh[(size_t)(m0 + row) * F + f] = acc[r];
    }
    __syncthreads();

    float ac1[8], ac2[8];
#pragma unroll
    for (int r = 0; r < 8; r++) { ac1[r] = 0.0f; ac2[r] = 0.0f; }

#pragma unroll 4
    for (int k = 0; k < F; k++) {
        const float a1v = __ldg(a + k * F + f);
        const float a2v = __ldg(a + (F + k) * F + f);
#pragma unroll
        for (int r = 0; r < 8; r++) {
            const float w = whs[(half * 8 + r) * F + k];
            ac1[r] = fmaf(w, a1v, ac1[r]);
            ac2[r] = fmaf(w, a2v, ac2[r]);
        }
    }

#pragma unroll
    for (int r = 0; r < 8; r++) {
        const int row = half * 8 + r;
        g_e1[(size_t)(m0 + row) * F + f] = ac1[r];
        g_e2[(size_t)(m0 + row) * F + f] = ac2[r];
    }
}

// ----------------------------------------------------------------------------
// Kernel 2: fused leakyrelu + mask + softmax(no-max, values are tiny) +
//           weighted sum (h_prime) + elu + streaming attention writeout.
// Block = (i-group of 4, t). 512 threads: f = tid&127, il = tid>>7.
// SMEM: e2 tile [128][128] + Wh tile [128][128] + adj rows [4][128] = 130.5 KB
// ----------------------------------------------------------------------------
#define IPB 4
#define ATTN_SMEM_BYTES ((V * F + V * F + IPB * V) * (int)sizeof(float))

__global__ void __launch_bounds__(512, 1) attn_fused(
    const float* __restrict__ adj,
    float* __restrict__ out)
{
    extern __shared__ float sm[];
    float* e2s  = sm;                 // V*F
    float* whs  = sm + V * F;         // V*F
    float* adjs = sm + 2 * V * F;     // IPB*V

    const int t   = blockIdx.y;
    const int ig  = blockIdx.x;
    const int tid = threadIdx.x;
    const int f   = tid & 127;
    const int il  = tid >> 7;
    const int i   = ig * IPB + il;

    // cooperative tile loads (4096 float4 per tile / 512 threads = 8 each)
    {
        const float4* se2 = (const float4*)(g_e2 + (size_t)t * V * F);
        const float4* swh = (const float4*)(g_Wh + (size_t)t * V * F);
        float4* de2 = (float4*)e2s;
        float4* dwh = (float4*)whs;
#pragma unroll
        for (int u = 0; u < 8; u++) {
            de2[tid + u * 512] = se2[tid + u * 512];
            dwh[tid + u * 512] = swh[tid + u * 512];
        }
        // adj rows for the IPB i's handled here (contiguous 512 floats)
        adjs[tid] = adj[(size_t)ig * (IPB * V) + tid];
    }
    const float e1v = g_e1[((size_t)t * V + i) * F + f];
    __syncthreads();

    const float* adjrow = adjs + il * V;

    // Pass A: sum of exp + weighted numerator (h_prime)
    float s = 0.0f, num = 0.0f;
#pragma unroll 4
    for (int j = 0; j < V; j++) {
        float v = e1v + e2s[j * F + f];
        v = fmaxf(v, LRELU_ALPHA * v);            // leaky relu
        const float p = (adjrow[j] > 0.0f) ? __expf(v) : 0.0f;
        s += p;
        num = fmaf(p, whs[j * F + f], num);
    }

    const float r = 1.0f / s;

    // h_prime -> elu -> out (first segment of tuple)
    {
        const float hp = num * r;
        out[((size_t)t * V + i) * F + f] = (hp > 0.0f) ? hp : expm1f(hp);
    }

    // Pass B: recompute exp, normalize, stream attention out
    float* ab = out + ATT_OFF + (((size_t)t * V + i) * V) * F + f;
#pragma unroll 4
    for (int j = 0; j < V; j++) {
        float v = e1v + e2s[j * F + f];
        v = fmaxf(v, LRELU_ALPHA * v);
        const float p = (adjrow[j] > 0.0f) ? __expf(v) * r : 0.0f;
        __stcs(ab + (size_t)j * F, p);
    }
}

// ----------------------------------------------------------------------------
extern "C" void kernel_launch(void* const* d_in, const int* in_sizes, int n_in,
                              void* d_out, int out_size)
{
    const float* h   = (const float*)d_in[0];   // [2560,128]
    const float* adj = (const float*)d_in[1];   // [128,128,1]
    const float* W   = (const float*)d_in[2];   // [128,128]
    const float* a   = (const float*)d_in[3];   // [256,128]
    float* out = (float*)d_out;

    cudaFuncSetAttribute(attn_fused, cudaFuncAttributeMaxDynamicSharedMemorySize,
                         ATTN_SMEM_BYTES);

    gemm_fused<<<(NTIME * V) / MT, 256>>>(h, W, a);

    dim3 grid(V / IPB, NTIME);
    attn_fused<<<grid, 512, ATTN_SMEM_BYTES>>>(adj, out);
}

// round 2
// speedup vs baseline: 1.4155x; 1.4155x over previous
#include <cuda_runtime.h>
#include <cstdint>
#include <cstddef>

#define NTIME 20
#define V     128
#define F     128
#define LRELU_ALPHA 0.2f

// out tuple layout: elu(h_prime) [20*128*128] then attention_raw [20*128*128*128]
#define OUT_HP_ELEMS   (NTIME * V * F)
#define ATT_OFF        OUT_HP_ELEMS

// Scratch (device globals: no allocation allowed in kernel_launch)
__device__ float g_Wh[NTIME * V * F];
__device__ float g_e1[NTIME * V * F];
__device__ float g_e2[NTIME * V * F];

// ----------------------------------------------------------------------------
// Kernel 1: fused  Wh = h @ W ;  e1 = Wh @ a[:128] ;  e2 = Wh @ a[128:]
// MT=8 rows per block, 256 threads (f = tid&127, half = tid>>7, 4 rows each).
// 320 blocks -> 2+ CTAs/SM.
// ----------------------------------------------------------------------------
#define MT 8

__global__ void __launch_bounds__(256) gemm_fused(
    const float* __restrict__ h,
    const float* __restrict__ W,
    const float* __restrict__ a)
{
    __shared__ float hs[MT * F];
    __shared__ float whs[MT * F];

    const int tid  = threadIdx.x;
    const int f    = tid & 127;
    const int half = tid >> 7;
    const int m0   = blockIdx.x * MT;

    // load h tile: MT*F = 1024 floats = 256 float4, one per thread
    ((float4*)hs)[tid] = ((const float4*)(h + (size_t)m0 * F))[tid];
    __syncthreads();

    float acc[4];
#pragma unroll
    for (int r = 0; r < 4; r++) acc[r] = 0.0f;

#pragma unroll 4
    for (int k = 0; k < F; k++) {
        const float wv = __ldg(W + k * F + f);
#pragma unroll
        for (int r = 0; r < 4; r++)
            acc[r] = fmaf(hs[(half * 4 + r) * F + k], wv, acc[r]);
    }

#pragma unroll
    for (int r = 0; r < 4; r++) {
        const int row = half * 4 + r;
        whs[row * F + f] = acc[r];
        g_Wh[(size_t)(m0 + row) * F + f] = acc[r];
    }
    __syncthreads();

    float ac1[4], ac2[4];
#pragma unroll
    for (int r = 0; r < 4; r++) { ac1[r] = 0.0f; ac2[r] = 0.0f; }

#pragma unroll 4
    for (int k = 0; k < F; k++) {
        const float a1v = __ldg(a + k * F + f);
        const float a2v = __ldg(a + (F + k) * F + f);
#pragma unroll
        for (int r = 0; r < 4; r++) {
            const float w = whs[(half * 4 + r) * F + k];
            ac1[r] = fmaf(w, a1v, ac1[r]);
            ac2[r] = fmaf(w, a2v, ac2[r]);
        }
    }

#pragma unroll
    for (int r = 0; r < 4; r++) {
        const int row = half * 4 + r;
        g_e1[(size_t)(m0 + row) * F + f] = ac1[r];
        g_e2[(size_t)(m0 + row) * F + f] = ac2[r];
    }
}

// ----------------------------------------------------------------------------
// Kernel 2: fused leakyrelu + mask + softmax + weighted sum + elu + attn write.
//
// Block = (t, f-half, i-group of 16). 512 threads = 16 warps.
// warp = one i; lane covers 2 consecutive f within the 64-wide f-half.
// -> adj[i][j] is WARP-UNIFORM: real branch skips exp/fma for masked j.
// smem = e2 half-tile (32KB) + Wh half-tile (32KB) + adj rows (8KB) = 72KB
// -> 2 CTAs/SM, 320 blocks ~ 1 wave on 296 slots.
// ----------------------------------------------------------------------------
#define FH 64                        // f per block
#define IPB 16                       // i per block
#define ATTN_SMEM_BYTES ((V * FH * 2 + IPB * V) * (int)sizeof(float))

__global__ void __launch_bounds__(512, 2) attn_fused(
    const float* __restrict__ adj,
    float* __restrict__ out)
{
    extern __shared__ float sm[];
    float* e2s  = sm;                 // [V][FH]
    float* whs  = sm + V * FH;        // [V][FH]
    float* adjs = sm + 2 * V * FH;    // [IPB][V]

    const int t    = blockIdx.y;
    const int bx   = blockIdx.x;      // 0..15
    const int fh   = bx & 1;
    const int ig   = bx >> 1;         // 0..7
    const int tid  = threadIdx.x;
    const int lane = tid & 31;
    const int il   = tid >> 5;        // warp id = local i
    const int i    = ig * IPB + il;
    const int f2   = fh * FH + lane * 2;

    // cooperative tile loads: each half-tile = V*FH floats = 2048 float4
    {
        const float* e2g = g_e2 + (size_t)t * V * F + fh * FH;
        const float* whg = g_Wh + (size_t)t * V * F + fh * FH;
#pragma unroll
        for (int u = 0; u < 4; u++) {
            const int idx = tid + u * 512;     // 0..2047
            const int j = idx >> 4, c = idx & 15;
            ((float4*)e2s)[idx] = *(const float4*)(e2g + j * F + c * 4);
            ((float4*)whs)[idx] = *(const float4*)(whg + j * F + c * 4);
        }
        // adj rows for i in [ig*16, ig*16+16): 2048 contiguous floats
        ((float4*)adjs)[tid] = ((const float4*)(adj + (size_t)ig * IPB * V))[tid];
    }

    const float2 e1v = *(const float2*)(g_e1 + ((size_t)t * V + i) * F + f2);
    __syncthreads();

    const float* adjrow = adjs + il * V;

    // Pass A: sum of exp + weighted numerator (warp-uniform branch on adj)
    float s0 = 0.0f, s1 = 0.0f, n0 = 0.0f, n1 = 0.0f;
#pragma unroll 4
    for (int j = 0; j < V; j++) {
        if (adjrow[j] > 0.0f) {
            const float2 e2v = *(const float2*)(e2s + j * FH + lane * 2);
            float v0 = e1v.x + e2v.x;
            float v1 = e1v.y + e2v.y;
            v0 = fmaxf(v0, LRELU_ALPHA * v0);
            v1 = fmaxf(v1, LRELU_ALPHA * v1);
            const float p0 = __expf(v0);
            const float p1 = __expf(v1);
            const float2 wv = *(const float2*)(whs + j * FH + lane * 2);
            s0 += p0;  s1 += p1;
            n0 = fmaf(p0, wv.x, n0);
            n1 = fmaf(p1, wv.y, n1);
        }
    }

    const float r0 = 1.0f / s0;
    const float r1 = 1.0f / s1;

    // h_prime -> elu -> out (first tuple segment)
    {
        const float hp0 = n0 * r0;
        const float hp1 = n1 * r1;
        float2 o;
        o.x = (hp0 > 0.0f) ? hp0 : expm1f(hp0);
        o.y = (hp1 > 0.0f) ? hp1 : expm1f(hp1);
        *(float2*)(out + ((size_t)t * V + i) * F + f2) = o;
    }

    // Pass B: recompute exp only for unmasked j; stream normalized attention
    float* ab = out + ATT_OFF + (((size_t)t * V + i) * V) * F + f2;
#pragma unroll 4
    for (int j = 0; j < V; j++) {
        float2 pv;
        if (adjrow[j] > 0.0f) {
            const float2 e2v = *(const float2*)(e2s + j * FH + lane * 2);
            float v0 = e1v.x + e2v.x;
            float v1 = e1v.y + e2v.y;
            v0 = fmaxf(v0, LRELU_ALPHA * v0);
            v1 = fmaxf(v1, LRELU_ALPHA * v1);
            pv.x = __expf(v0) * r0;
            pv.y = __expf(v1) * r1;
        } else {
            pv.x = 0.0f; pv.y = 0.0f;
        }
        __stcs((float2*)(ab + (size_t)j * F), pv);
    }
}

// ----------------------------------------------------------------------------
extern "C" void kernel_launch(void* const* d_in, const int* in_sizes, int n_in,
                              void* d_out, int out_size)
{
    const float* h   = (const float*)d_in[0];   // [2560,128]
    const float* adj = (const float*)d_in[1];   // [128,128,1]
    const float* W   = (const float*)d_in[2];   // [128,128]
    const float* a   = (const float*)d_in[3];   // [256,128]
    float* out = (float*)d_out;

    cudaFuncSetAttribute(attn_fused, cudaFuncAttributeMaxDynamicSharedMemorySize,
                         ATTN_SMEM_BYTES);

    gemm_fused<<<(NTIME * V) / MT, 256>>>(h, W, a);

    dim3 grid(16, NTIME);
    attn_fused<<<grid, 512, ATTN_SMEM_BYTES>>>(adj, out);
}